// round 14
// baseline (speedup 1.0000x reference)
#include <cuda_runtime.h>
#include <cstdint>

// Problem constants
#define TT      512
#define BB      256
#define HH      128
#define EE      256
#define VV      82
#define HE      384     // HIDDEN + EMBED
#define G3H     384     // 3 gates * H

// Precomputed x-projection table: xtable[v][g*H+u], g: 0=f, 1=o, 2=c_tilde
__device__ float g_xtable[VV * G3H];

__device__ __forceinline__ unsigned long long ffma2(unsigned long long a,
                                                    unsigned long long b,
                                                    unsigned long long c) {
    unsigned long long d;
    asm("fma.rn.f32x2 %0, %1, %2, %3;" : "=l"(d) : "l"(a), "l"(b), "l"(c));
    return d;
}

__device__ __forceinline__ float2 unpack2(unsigned long long v) {
    float2 r;
    asm("mov.b64 {%0, %1}, %2;" : "=f"(r.x), "=f"(r.y) : "l"(v));
    return r;
}

__device__ __forceinline__ float tanh_hw(float x) {
    float y;
    asm("tanh.approx.f32 %0, %1;" : "=f"(y) : "f"(x));
    return y;
}

// ---------------------------------------------------------------------------
// Kernel 1: xtable[v][g*128+u] = sum_k emb[v][k] * W_g[u][128+k]
// ---------------------------------------------------------------------------
__global__ void xtable_kernel(const float* __restrict__ emb,
                              const float* __restrict__ Wf,
                              const float* __restrict__ Wc,
                              const float* __restrict__ Wo) {
    int v = blockIdx.x;          // 0..81
    int j = threadIdx.x;         // 0..383
    int g = j >> 7;
    int u = j & 127;
    const float* W = (g == 0) ? Wf : ((g == 1) ? Wo : Wc);
    const float4* wrow = reinterpret_cast<const float4*>(W + (size_t)u * HE + HH);
    const float4* e = reinterpret_cast<const float4*>(emb + (size_t)v * EE);
    float s = 0.0f;
#pragma unroll
    for (int k = 0; k < EE / 4; k++) {
        float4 a = e[k];
        float4 b = wrow[k];
        s += a.x * b.x + a.y * b.y + a.z * b.z + a.w * b.w;
    }
    g_xtable[v * G3H + j] = s;
}

// ---------------------------------------------------------------------------
// Kernel 2: recurrence. 128 blocks x 512 threads; block owns 2 batch rows.
// Lane bits: s = lane&7 (unit slot), bsel = bit3 (owned batch),
//            kh = bit4 (owned K-half), qq = (kh<<1)|bsel (W K-quarter).
// Thread owns W_f/W_o/W_c row u = warp*8+s, K-cols [qq*32, qq*32+32).
// Single pass over each h vector (no spills):
//   phase 1: not-owned batch, all 3 gates; xor8 batch-exchange (hidden
//   under phase 2); phase 2: owned batch; xor16 K-half reduce.
// Tail scheduling: prefetch LDGs between the shuffles and the activations;
// MUFUs spaced (T, gc | LDGs | go, th) to de-burst the rt-8 MUFU pipe.
// creg/th maintained unconditionally (kh pair identical); predicated h STS.
// ONE __syncthreads per step; gate STGs after the barrier.
// ---------------------------------------------------------------------------
__global__ void __launch_bounds__(512, 1)
lstm_kernel(const int*   __restrict__ tokens,   // [B, T]
            const float* __restrict__ Wf,
            const float* __restrict__ Wc,
            const float* __restrict__ Wo,
            const float* __restrict__ clfW,     // [V, H]
            const float* __restrict__ clfb,     // [V]
            float* __restrict__ out) {
    // [buf][batch][skewed 128]: quarter qq at float offset qq*36 (bank skew)
    __shared__ __align__(16) float sh_h[2][2][144];
    __shared__ int sh_tok[2][TT + 1];   // PRE-SCALED: tok * G3H; +1 pad slot

    const int j    = threadIdx.x;        // 0..511
    const int lane = j & 31;
    const int warp = j >> 5;             // 0..15
    const int s    = lane & 7;
    const int bsel = (lane >> 3) & 1;    // owned batch
    const int kh   = lane >> 4;          // owned K-half
    const int qq   = (lane >> 3) & 3;    // W K-quarter = (kh<<1)|bsel
    const int u    = warp * 8 + s;       // unit 0..127
    const int b0   = blockIdx.x * 2;

    // ---- load W rows (3 gates), K-quarter segment: 3 x 16 packed f32x2 ----
    unsigned long long wf[16], wo[16], wc[16];
    {
        const ulonglong2* pf = reinterpret_cast<const ulonglong2*>(Wf + (size_t)u * HE + qq * 32);
        const ulonglong2* po = reinterpret_cast<const ulonglong2*>(Wo + (size_t)u * HE + qq * 32);
        const ulonglong2* pc = reinterpret_cast<const ulonglong2*>(Wc + (size_t)u * HE + qq * 32);
#pragma unroll
        for (int i = 0; i < 8; i++) {
            ulonglong2 tf = pf[i]; wf[2 * i] = tf.x; wf[2 * i + 1] = tf.y;
            ulonglong2 to = po[i]; wo[2 * i] = to.x; wo[2 * i + 1] = to.y;
            ulonglong2 tc = pc[i]; wc[2 * i] = tc.x; wc[2 * i + 1] = tc.y;
        }
    }

    // ---- init h buffers = 0; stage PRE-SCALED tokens (pad slot = 0) ----
    for (int i = j; i < 2 * 2 * 144; i += 512) (&sh_h[0][0][0])[i] = 0.0f;
    for (int i = j; i < 2 * TT; i += 512) {
        const int b = i >> 9, t = i & 511;
        sh_tok[b][t] = tokens[(size_t)(b0 + b) * TT + t] * G3H;
    }
    if (j < 2) sh_tok[j][TT] = 0;
    __syncthreads();

    float creg = 0.0f;                   // cell state (all lanes; kh pair identical)

    const size_t gateSz = (size_t)TT * BB * HH;
    float* __restrict__ f_out = out + (size_t)BB * VV;
    float* __restrict__ o_out = f_out + gateSz;
    float* __restrict__ c_out = o_out + gateSz;

    const float* gx = g_xtable + u;      // per-thread xtable base
    const int* tokp = &sh_tok[bsel][0];  // owned-batch token row
    const int qoff = qq * 36;            // skewed smem quarter base (floats)
    int off = (b0 + bsel) * HH + u;      // 32-bit running output offset

    const unsigned FULL = 0xffffffffu;

    // x for step 0; f/o components PRE-SCALED by 0.5 (sigmoid-as-tanh form)
    int toff = tokp[0];
    float xf05 = 0.5f * __ldg(gx + toff);
    float xo05 = 0.5f * __ldg(gx + toff + HH);
    float xc   = __ldg(gx + toff + 2 * HH);

    // one step: read h from buffer rb, write h to buffer wb
    auto step = [&](int t, int rb, int wb) {
        // hoist next-token read out of the epilogue chain
        const int toffn = tokp[t + 1];

        // ---------- PHASE 1: NOT-owned batch partials (all 3 gates) ----------
        const ulonglong2* hN = reinterpret_cast<const ulonglong2*>(&sh_h[rb][bsel ^ 1][qoff]);
        unsigned long long anf = 0ull, ano = 0ull, anc = 0ull;
#pragma unroll
        for (int i = 0; i < 8; i++) {
            ulonglong2 v = hN[i];
            anf = ffma2(v.x, wf[2 * i], anf); anf = ffma2(v.y, wf[2 * i + 1], anf);
            ano = ffma2(v.x, wo[2 * i], ano); ano = ffma2(v.y, wo[2 * i + 1], ano);
            anc = ffma2(v.x, wc[2 * i], anc); anc = ffma2(v.y, wc[2 * i + 1], anc);
        }
        float2 P;
        P = unpack2(anf); const float snf = P.x + P.y;
        P = unpack2(ano); const float sno = P.x + P.y;
        P = unpack2(anc); const float snc = P.x + P.y;

        // xor8 exchange: send my not-owned partial; receive my missing
        // quarter (qq^1) for MY batch. Latency hidden by PHASE 2.
        const float rf = __shfl_xor_sync(FULL, snf, 8);
        const float ro = __shfl_xor_sync(FULL, sno, 8);
        const float rc = __shfl_xor_sync(FULL, snc, 8);

        // ---------- PHASE 2: owned batch partials (single pass) ----------
        const ulonglong2* hO = reinterpret_cast<const ulonglong2*>(&sh_h[rb][bsel][qoff]);
        unsigned long long aof = 0ull, aoo = 0ull, aoc = 0ull;
#pragma unroll
        for (int i = 0; i < 8; i++) {
            ulonglong2 v = hO[i];
            aof = ffma2(v.x, wf[2 * i], aof); aof = ffma2(v.y, wf[2 * i + 1], aof);
            aoo = ffma2(v.x, wo[2 * i], aoo); aoo = ffma2(v.y, wo[2 * i + 1], aoo);
            aoc = ffma2(v.x, wc[2 * i], aoc); aoc = ffma2(v.y, wc[2 * i + 1], aoc);
        }
        P = unpack2(aof); float Sf = P.x + P.y + rf;
        P = unpack2(aoc); float Sc = P.x + P.y + rc;
        P = unpack2(aoo); float So = P.x + P.y + ro;

        // xor16: K-half reduce (f and c first -- they gate the c-chain)
        Sf += __shfl_xor_sync(FULL, Sf, 16);
        Sc += __shfl_xor_sync(FULL, Sc, 16);
        So += __shfl_xor_sync(FULL, So, 16);

        // first two MUFUs issue as soon as Sf/Sc land
        const float T  = tanh_hw(fmaf(0.5f, Sf, xf05));  // gf = 0.5T + 0.5
        const float gc = tanh_hw(Sc + xc);

        // prefetch x(t+1) HERE: fills the MUFU shadow, and its latency is
        // covered by the rest of the tail + the next step's FMA window
        const float nxf = __ldg(gx + toffn);
        const float nxo = __ldg(gx + toffn + HH);
        const float nxc = __ldg(gx + toffn + 2 * HH);

        // remaining MUFUs, spaced after the LDG issue slots
        const float go = fmaf(0.5f, tanh_hw(fmaf(0.5f, So, xo05)), 0.5f);
        const float gf = fmaf(0.5f, T, 0.5f);

        // c-chain (kh pair holds identical values -> no branch)
        creg = fmaf(0.5f * T, creg - gc, 0.5f * (creg + gc));
        const float th = tanh_hw(creg);

        // commit prefetched x (pre-scaling on the ALU/FMA slack)
        xf05 = 0.5f * nxf;
        xo05 = 0.5f * nxo;
        xc   = nxc;

        // critical path end: predicated h STS (kh==0 lanes), then barrier
        if (kh == 0) {
            sh_h[wb][bsel][u + (u >> 5) * 4] = go * th;
        }
        __syncthreads();

        // gate STGs off the critical path
        if (kh == 0) {
            f_out[off] = gf;
        } else {
            o_out[off] = go;
            c_out[off] = gc;
        }
        off += BB * HH;
    };

#pragma unroll 1
    for (int t = 0; t < TT; t += 2) {
        step(t, 0, 1);
        step(t + 1, 1, 0);
    }

    // ---- logits: h_T @ clf_W.T + clf_b  (final h in buffer 0) ----
    if (j < 2 * VV) {
        const int b = j / VV;
        const int v = j % VV;
        float sacc = clfb[v];
        const float* wcf = clfW + (size_t)v * HH;
#pragma unroll 8
        for (int k = 0; k < HH; k++)
            sacc += sh_h[0][b][k + (k >> 5) * 4] * wcf[k];
        out[(size_t)(b0 + b) * VV + v] = sacc;
    }
}

// ---------------------------------------------------------------------------
// kernel_launch
// Inputs (metadata order): batch_reviews(int32 [256,512]), emb(f32 [82,256]),
//   W_f(f32 [128,384]), W_c(f32 [128,384]), W_o(f32 [128,384]),
//   clf_W(f32 [82,128]), clf_b(f32 [82])
// Output (f32): logits [256*82] | f_all [512*256*128] | o_all | ct_all
// ---------------------------------------------------------------------------
extern "C" void kernel_launch(void* const* d_in, const int* in_sizes, int n_in,
                              void* d_out, int out_size) {
    const int*   tokens = (const int*)  d_in[0];
    const float* emb    = (const float*)d_in[1];
    const float* Wf     = (const float*)d_in[2];
    const float* Wc     = (const float*)d_in[3];
    const float* Wo     = (const float*)d_in[4];
    const float* clfW   = (const float*)d_in[5];
    const float* clfb   = (const float*)d_in[6];
    float* out = (float*)d_out;

    xtable_kernel<<<VV, G3H>>>(emb, Wf, Wc, Wo);
    lstm_kernel<<<BB / 2, 512>>>(tokens, Wf, Wc, Wo, clfW, clfb, out);
}

// round 15
// speedup vs baseline: 1.0555x; 1.0555x over previous
#include <cuda_runtime.h>
#include <cstdint>

// Problem constants
#define TT      512
#define BB      256
#define HH      128
#define EE      256
#define VV      82
#define HE      384     // HIDDEN + EMBED
#define G3H     384     // 3 gates * H

// Precomputed x-projection table: xtable[v][g*H+u], g: 0=f, 1=o, 2=c_tilde
__device__ float g_xtable[VV * G3H];

__device__ __forceinline__ unsigned long long ffma2(unsigned long long a,
                                                    unsigned long long b,
                                                    unsigned long long c) {
    unsigned long long d;
    asm("fma.rn.f32x2 %0, %1, %2, %3;" : "=l"(d) : "l"(a), "l"(b), "l"(c));
    return d;
}

__device__ __forceinline__ float2 unpack2(unsigned long long v) {
    float2 r;
    asm("mov.b64 {%0, %1}, %2;" : "=f"(r.x), "=f"(r.y) : "l"(v));
    return r;
}

__device__ __forceinline__ float tanh_hw(float x) {
    float y;
    asm("tanh.approx.f32 %0, %1;" : "=f"(y) : "f"(x));
    return y;
}

// ---------------------------------------------------------------------------
// Kernel 1: xtable[v][g*128+u] = sum_k emb[v][k] * W_g[u][128+k]
// ---------------------------------------------------------------------------
__global__ void xtable_kernel(const float* __restrict__ emb,
                              const float* __restrict__ Wf,
                              const float* __restrict__ Wc,
                              const float* __restrict__ Wo) {
    int v = blockIdx.x;          // 0..81
    int j = threadIdx.x;         // 0..383
    int g = j >> 7;
    int u = j & 127;
    const float* W = (g == 0) ? Wf : ((g == 1) ? Wo : Wc);
    const float4* wrow = reinterpret_cast<const float4*>(W + (size_t)u * HE + HH);
    const float4* e = reinterpret_cast<const float4*>(emb + (size_t)v * EE);
    float s = 0.0f;
#pragma unroll
    for (int k = 0; k < EE / 4; k++) {
        float4 a = e[k];
        float4 b = wrow[k];
        s += a.x * b.x + a.y * b.y + a.z * b.z + a.w * b.w;
    }
    g_xtable[v * G3H + j] = s;
}

// ---------------------------------------------------------------------------
// Kernel 2: recurrence. 128 blocks x 512 threads; block owns 2 batch rows.
// Lane bits: s = lane&7 (unit slot), bsel = bit3 (owned batch),
//            kh = bit4 (owned K-half), qq = (kh<<1)|bsel (W K-quarter).
// Thread owns W_f/W_o/W_c row u = warp*8+s, K-cols [qq*32, qq*32+32).
// Single pass over each h vector (no spills):
//   phase 1: not-owned batch, all 3 gates; xor8 batch-exchange (hidden
//   under phase 2); phase 2: owned batch; xor16 K-half reduce.
// Epilogue (R12 proven ordering): x pre-scaled by 0.5 folds the sigmoid
// into one FMA; activations first, then c-chain (unconditional -- kh pair
// identical), THEN x(t+1) prefetch, predicated h STS, barrier, gate STGs.
// Loop-invariant hoists: skewed h STS index, write-buffer addresses.
// ---------------------------------------------------------------------------
__global__ void __launch_bounds__(512, 1)
lstm_kernel(const int*   __restrict__ tokens,   // [B, T]
            const float* __restrict__ Wf,
            const float* __restrict__ Wc,
            const float* __restrict__ Wo,
            const float* __restrict__ clfW,     // [V, H]
            const float* __restrict__ clfb,     // [V]
            float* __restrict__ out) {
    // [buf][batch][skewed 128]: quarter qq at float offset qq*36 (bank skew)
    __shared__ __align__(16) float sh_h[2][2][144];
    __shared__ int sh_tok[2][TT + 1];   // PRE-SCALED: tok * G3H; +1 pad slot

    const int j    = threadIdx.x;        // 0..511
    const int lane = j & 31;
    const int warp = j >> 5;             // 0..15
    const int s    = lane & 7;
    const int bsel = (lane >> 3) & 1;    // owned batch
    const int kh   = lane >> 4;          // owned K-half
    const int qq   = (lane >> 3) & 3;    // W K-quarter = (kh<<1)|bsel
    const int u    = warp * 8 + s;       // unit 0..127
    const int b0   = blockIdx.x * 2;

    // ---- load W rows (3 gates), K-quarter segment: 3 x 16 packed f32x2 ----
    unsigned long long wf[16], wo[16], wc[16];
    {
        const ulonglong2* pf = reinterpret_cast<const ulonglong2*>(Wf + (size_t)u * HE + qq * 32);
        const ulonglong2* po = reinterpret_cast<const ulonglong2*>(Wo + (size_t)u * HE + qq * 32);
        const ulonglong2* pc = reinterpret_cast<const ulonglong2*>(Wc + (size_t)u * HE + qq * 32);
#pragma unroll
        for (int i = 0; i < 8; i++) {
            ulonglong2 tf = pf[i]; wf[2 * i] = tf.x; wf[2 * i + 1] = tf.y;
            ulonglong2 to = po[i]; wo[2 * i] = to.x; wo[2 * i + 1] = to.y;
            ulonglong2 tc = pc[i]; wc[2 * i] = tc.x; wc[2 * i + 1] = tc.y;
        }
    }

    // ---- init h buffers = 0; stage PRE-SCALED tokens (pad slot = 0) ----
    for (int i = j; i < 2 * 2 * 144; i += 512) (&sh_h[0][0][0])[i] = 0.0f;
    for (int i = j; i < 2 * TT + 2; i += 512) {
        const int b = i > TT ? 1 : 0;            // covers both rows + pads
        const int t = i - b * (TT + 1);
        sh_tok[b][t] = (t < TT)
            ? tokens[(size_t)(b0 + b) * TT + t] * G3H : 0;
    }
    __syncthreads();

    float creg = 0.0f;                   // cell state (all lanes; kh pair identical)

    const size_t gateSz = (size_t)TT * BB * HH;
    float* __restrict__ f_out = out + (size_t)BB * VV;
    float* __restrict__ o_out = f_out + gateSz;
    float* __restrict__ c_out = o_out + gateSz;

    const float* gx = g_xtable + u;      // per-thread xtable base
    const int* tokp = &sh_tok[bsel][0];  // owned-batch token row
    const int qoff = qq * 36;            // skewed smem quarter base (floats)
    int off = (b0 + bsel) * HH + u;      // 32-bit running output offset

    // loop-invariant: skewed h write slots for both buffers
    const int uskew = u + (u >> 5) * 4;
    float* const hw0 = &sh_h[0][bsel][uskew];
    float* const hw1 = &sh_h[1][bsel][uskew];

    const unsigned FULL = 0xffffffffu;

    // x for step 0; f/o components PRE-SCALED by 0.5 (sigmoid-as-tanh form)
    int toff = tokp[0];
    float xf05 = 0.5f * __ldg(gx + toff);
    float xo05 = 0.5f * __ldg(gx + toff + HH);
    float xc   = __ldg(gx + toff + 2 * HH);

    // one step: read h from buffer rb, write h into hw (skewed slot)
    auto step = [&](int t, int rb, float* hw) {
        // hoist next-token read out of the epilogue chain
        const int toffn = tokp[t + 1];

        // ---------- PHASE 1: NOT-owned batch partials (all 3 gates) ----------
        const ulonglong2* hN = reinterpret_cast<const ulonglong2*>(&sh_h[rb][bsel ^ 1][qoff]);
        unsigned long long anf = 0ull, ano = 0ull, anc = 0ull;
#pragma unroll
        for (int i = 0; i < 8; i++) {
            ulonglong2 v = hN[i];
            anf = ffma2(v.x, wf[2 * i], anf); anf = ffma2(v.y, wf[2 * i + 1], anf);
            ano = ffma2(v.x, wo[2 * i], ano); ano = ffma2(v.y, wo[2 * i + 1], ano);
            anc = ffma2(v.x, wc[2 * i], anc); anc = ffma2(v.y, wc[2 * i + 1], anc);
        }
        float2 P;
        P = unpack2(anf); const float snf = P.x + P.y;
        P = unpack2(ano); const float sno = P.x + P.y;
        P = unpack2(anc); const float snc = P.x + P.y;

        // xor8 exchange: send my not-owned partial; receive my missing
        // quarter (qq^1) for MY batch. Latency hidden by PHASE 2.
        const float rf = __shfl_xor_sync(FULL, snf, 8);
        const float ro = __shfl_xor_sync(FULL, sno, 8);
        const float rc = __shfl_xor_sync(FULL, snc, 8);

        // ---------- PHASE 2: owned batch partials (single pass) ----------
        const ulonglong2* hO = reinterpret_cast<const ulonglong2*>(&sh_h[rb][bsel][qoff]);
        unsigned long long aof = 0ull, aoo = 0ull, aoc = 0ull;
#pragma unroll
        for (int i = 0; i < 8; i++) {
            ulonglong2 v = hO[i];
            aof = ffma2(v.x, wf[2 * i], aof); aof = ffma2(v.y, wf[2 * i + 1], aof);
            aoo = ffma2(v.x, wo[2 * i], aoo); aoo = ffma2(v.y, wo[2 * i + 1], aoo);
            aoc = ffma2(v.x, wc[2 * i], aoc); aoc = ffma2(v.y, wc[2 * i + 1], aoc);
        }
        P = unpack2(aof); float Sf = P.x + P.y + rf;
        P = unpack2(aoc); float Sc = P.x + P.y + rc;
        P = unpack2(aoo); float So = P.x + P.y + ro;

        // xor16: K-half reduce (f and c first -- they gate the c-chain)
        Sf += __shfl_xor_sync(FULL, Sf, 16);
        Sc += __shfl_xor_sync(FULL, Sc, 16);
        So += __shfl_xor_sync(FULL, So, 16);

        // activations: x folded into the FMA (pre-scaled), T/gc issue first
        const float T  = tanh_hw(fmaf(0.5f, Sf, xf05));  // gf = 0.5T + 0.5
        const float gc = tanh_hw(Sc + xc);
        const float go = fmaf(0.5f, tanh_hw(fmaf(0.5f, So, xo05)), 0.5f);
        const float gf = fmaf(0.5f, T, 0.5f);

        // c-chain unconditional (kh pair holds identical values -> no branch)
        creg = fmaf(0.5f * T, creg - gc, 0.5f * (creg + gc));
        const float th = tanh_hw(creg);

        // prefetch x(t+1) AFTER activations consumed x(t); crosses the
        // barrier + the next step's full FMA window
        xf05 = 0.5f * __ldg(gx + toffn);
        xo05 = 0.5f * __ldg(gx + toffn + HH);
        xc   = __ldg(gx + toffn + 2 * HH);

        // critical path end: predicated h STS (kh==0 lanes), then barrier
        if (kh == 0) {
            *hw = go * th;
        }
        __syncthreads();

        // gate STGs off the critical path
        if (kh == 0) {
            f_out[off] = gf;
        } else {
            o_out[off] = go;
            c_out[off] = gc;
        }
        off += BB * HH;
    };

#pragma unroll 1
    for (int t = 0; t < TT; t += 2) {
        step(t, 0, hw1);
        step(t + 1, 1, hw0);
    }

    // ---- logits: h_T @ clf_W.T + clf_b  (final h in buffer 0) ----
    if (j < 2 * VV) {
        const int b = j / VV;
        const int v = j % VV;
        float sacc = clfb[v];
        const float* wcf = clfW + (size_t)v * HH;
#pragma unroll 8
        for (int k = 0; k < HH; k++)
            sacc += sh_h[0][b][k + (k >> 5) * 4] * wcf[k];
        out[(size_t)(b0 + b) * VV + v] = sacc;
    }
}

// ---------------------------------------------------------------------------
// kernel_launch
// Inputs (metadata order): batch_reviews(int32 [256,512]), emb(f32 [82,256]),
//   W_f(f32 [128,384]), W_c(f32 [128,384]), W_o(f32 [128,384]),
//   clf_W(f32 [82,128]), clf_b(f32 [82])
// Output (f32): logits [256*82] | f_all [512*256*128] | o_all | ct_all
// ---------------------------------------------------------------------------
extern "C" void kernel_launch(void* const* d_in, const int* in_sizes, int n_in,
                              void* d_out, int out_size) {
    const int*   tokens = (const int*)  d_in[0];
    const float* emb    = (const float*)d_in[1];
    const float* Wf     = (const float*)d_in[2];
    const float* Wc     = (const float*)d_in[3];
    const float* Wo     = (const float*)d_in[4];
    const float* clfW   = (const float*)d_in[5];
    const float* clfb   = (const float*)d_in[6];
    float* out = (float*)d_out;

    xtable_kernel<<<VV, G3H>>>(emb, Wf, Wc, Wo);
    lstm_kernel<<<BB / 2, 512>>>(tokens, Wf, Wc, Wo, clfW, clfb, out);
}